// round 8
// baseline (speedup 1.0000x reference)
#include <cuda_runtime.h>
#include <stdint.h>

// Lukasiewicz t-norm feature expansion, compile-time-unrolled.
//   out[:, 0:16)    = x
//   out[:, 16:136)  = max(x[i]+x[j] - 1, 0)       i<j    (120)
//   out[:, 136:696) = max(x[i]+x[j]+x[k] - 2, 0)  i<j<k  (560)
// N = 131072 rows, 696 out cols (= 174 float4). Store-BW bound.
//
// Lane = row (x in registers, indices compile-time). Output staged per-warp
// in shared in 8-float4 column chunks, copied out coalesced (4 rows x 8
// float4 per STG iteration). Plain stores (streaming __stcs regressed DRAM
// throughput 64.8% -> 52.9% in R6).

#define N_ROWS   131072
#define OUT_V4   174
#define CH_V4    8             // float4 columns per chunk
#define NCHUNK   22            // 21 full chunks + overlapped tail (base 166)
#define WARPS_PB 4
#define BLOCK_T  (WARPS_PB * 32)

struct TabT {
    unsigned char k[696], a[696], b[696], c[696];
};

__host__ __device__ constexpr TabT make_tab() {
    TabT t{};
    int n = 0;
    for (int i = 0; i < 16; ++i) {
        t.k[n] = 1; t.a[n] = (unsigned char)i; t.b[n] = 0; t.c[n] = 0; ++n;
    }
    for (int i = 0; i < 16; ++i)
        for (int j = i + 1; j < 16; ++j) {
            t.k[n] = 2; t.a[n] = (unsigned char)i; t.b[n] = (unsigned char)j;
            t.c[n] = 0; ++n;
        }
    for (int i = 0; i < 16; ++i)
        for (int j = i + 1; j < 16; ++j)
            for (int l = j + 1; l < 16; ++l) {
                t.k[n] = 3; t.a[n] = (unsigned char)i; t.b[n] = (unsigned char)j;
                t.c[n] = (unsigned char)l; ++n;
            }
    return t;
}
__device__ constexpr TabT TAB = make_tab();

__global__ void __launch_bounds__(BLOCK_T, 8)
luk_kernel(const float4* __restrict__ x4, float4* __restrict__ out4)
{
    const int tid  = threadIdx.x;
    const int warp = tid >> 5;
    const int lane = tid & 31;

    const long long tileRow = ((long long)blockIdx.x * WARPS_PB + warp) * 32;
    const long long myRow   = tileRow + lane;

    // Load this lane's row (16 floats) into registers.
    float xv[16];
    {
        const float4 v0 = x4[myRow * 4 + 0];
        const float4 v1 = x4[myRow * 4 + 1];
        const float4 v2 = x4[myRow * 4 + 2];
        const float4 v3 = x4[myRow * 4 + 3];
        xv[0]=v0.x;  xv[1]=v0.y;  xv[2]=v0.z;  xv[3]=v0.w;
        xv[4]=v1.x;  xv[5]=v1.y;  xv[6]=v1.z;  xv[7]=v1.w;
        xv[8]=v2.x;  xv[9]=v2.y;  xv[10]=v2.z; xv[11]=v2.w;
        xv[12]=v3.x; xv[13]=v3.y; xv[14]=v3.z; xv[15]=v3.w;
    }

    // Per-warp staging: [32 rows][9 float4] -> stride 36 floats; bank-group
    // 4*lane mod 32 => conflict-free in quarter-warp STS.128/LDS.128 phases.
    __shared__ float4 sh[WARPS_PB][32][CH_V4 + 1];
    float4* __restrict__ mysh = &sh[warp][lane][0];

    // Copy-out mapping: 4 rows x 8 float4 per STG iteration.
    const int coRow = lane >> 3;        // 0..3
    const int coCol = lane & 7;         // 0..7
    float4* __restrict__ opBase =
        out4 + (tileRow + coRow) * OUT_V4 + coCol;

#pragma unroll
    for (int ch = 0; ch < NCHUNK; ++ch) {
        const int baseV4 = (ch == NCHUNK - 1) ? (OUT_V4 - CH_V4) : ch * CH_V4;
        const int base   = baseV4 * 4;

        // ---- compute phase: this lane's row, 32 columns, all-register ----
#pragma unroll
        for (int v = 0; v < CH_V4; ++v) {
            float r[4];
#pragma unroll
            for (int e = 0; e < 4; ++e) {
                const int col = base + v * 4 + e;
                const int K = TAB.k[col];
                const int A = TAB.a[col];
                const int B = TAB.b[col];
                const int C = TAB.c[col];
                if (K == 1)      r[e] = xv[A];
                else if (K == 2) r[e] = fmaxf(xv[A] + xv[B] - 1.0f, 0.0f);
                else             r[e] = fmaxf(xv[A] + (xv[B] + xv[C]) - 2.0f, 0.0f);
            }
            mysh[v] = make_float4(r[0], r[1], r[2], r[3]);
        }
        __syncwarp();

        // ---- copy-out: 8 iterations x (4 rows x 8 float4), plain STG.128 ----
#pragma unroll
        for (int t = 0; t < 8; ++t) {
            const float4 val = sh[warp][t * 4 + coRow][coCol];
            opBase[(long long)t * (4 * OUT_V4) + baseV4] = val;
        }
        __syncwarp();
    }
}

extern "C" void kernel_launch(void* const* d_in, const int* in_sizes, int n_in,
                              void* d_out, int out_size)
{
    const float4* x4 = (const float4*)d_in[0];
    float4* out4 = (float4*)d_out;
    (void)in_sizes; (void)n_in; (void)out_size;

    const int grid = N_ROWS / (WARPS_PB * 32);   // 1024 blocks
    luk_kernel<<<grid, BLOCK_T>>>(x4, out4);
}

// round 9
// speedup vs baseline: 1.1863x; 1.1863x over previous
#include <cuda_runtime.h>
#include <stdint.h>

// Lukasiewicz t-norm feature expansion — full-tile staging + linear stores.
//   out[:, 0:16)    = x
//   out[:, 16:136)  = max(x[i]+x[j] - 1, 0)       i<j    (120)
//   out[:, 136:696) = max(x[i]+x[j]+x[k] - 2, 0)  i<j<k  (560)
// N = 131072 rows, 696 out cols (174 float4). Store-BW bound.
//
// Block = 128 threads, 32 consecutive rows. Each warp computes a quarter of
// the 174 float4 columns for ALL 32 rows (lane = row, x in registers, all
// combination indices compile-time). Tile staged in dynamic shared
// ([32][175] float4, stride padded for conflict-free STS.128), then copied
// out as one contiguous 89,088B span: every warp STG.128 is a full aligned
// 512B run -> zero partial-line DRAM traffic (R4/R8 showed misaligned row
// segments inflate line traffic 1.375-1.75x).

#define N_ROWS    131072
#define ROWS_PB   32
#define OUT_V4    174
#define SH_STRIDE 175                         // float4; pad for bank spread
#define TILE_V4   (ROWS_PB * OUT_V4)          // 5568 float4 per block
#define SMEM_BYTES (ROWS_PB * SH_STRIDE * 16) // 89,600 B
#define BLOCK_T   128

struct TabT {
    unsigned char k[696], a[696], b[696], c[696];
};

__host__ __device__ constexpr TabT make_tab() {
    TabT t{};
    int n = 0;
    for (int i = 0; i < 16; ++i) {
        t.k[n] = 1; t.a[n] = (unsigned char)i; t.b[n] = 0; t.c[n] = 0; ++n;
    }
    for (int i = 0; i < 16; ++i)
        for (int j = i + 1; j < 16; ++j) {
            t.k[n] = 2; t.a[n] = (unsigned char)i; t.b[n] = (unsigned char)j;
            t.c[n] = 0; ++n;
        }
    for (int i = 0; i < 16; ++i)
        for (int j = i + 1; j < 16; ++j)
            for (int l = j + 1; l < 16; ++l) {
                t.k[n] = 3; t.a[n] = (unsigned char)i; t.b[n] = (unsigned char)j;
                t.c[n] = (unsigned char)l; ++n;
            }
    return t;
}
__device__ constexpr TabT TAB = make_tab();

// Compute float4 columns [LO, HI) of this lane's row into shared.
// All TAB indices are literals after unroll -> pure FADD/FMNMX.
template <int LO, int HI>
__device__ __forceinline__ void compute_cols(const float xv[16],
                                             float4* __restrict__ shrow)
{
#pragma unroll
    for (int v4 = LO; v4 < HI; ++v4) {
        float r[4];
#pragma unroll
        for (int e = 0; e < 4; ++e) {
            const int col = v4 * 4 + e;
            const int K = TAB.k[col];
            const int A = TAB.a[col];
            const int B = TAB.b[col];
            const int C = TAB.c[col];
            if (K == 1)      r[e] = xv[A];
            else if (K == 2) r[e] = fmaxf(xv[A] + xv[B] - 1.0f, 0.0f);
            else             r[e] = fmaxf(xv[A] + (xv[B] + xv[C]) - 2.0f, 0.0f);
        }
        shrow[v4] = make_float4(r[0], r[1], r[2], r[3]);
    }
}

__global__ void __launch_bounds__(BLOCK_T)
luk_kernel(const float4* __restrict__ x4, float4* __restrict__ out4)
{
    extern __shared__ float4 sh[];   // [ROWS_PB][SH_STRIDE]

    const int tid  = threadIdx.x;
    const int warp = tid >> 5;
    const int lane = tid & 31;

    const long long tileRow = (long long)blockIdx.x * ROWS_PB;
    const long long myRow   = tileRow + lane;

    // Load this lane's row (16 floats) into registers (same rows in all
    // 4 warps; redundant loads hit L1).
    float xv[16];
    {
        const float4 v0 = x4[myRow * 4 + 0];
        const float4 v1 = x4[myRow * 4 + 1];
        const float4 v2 = x4[myRow * 4 + 2];
        const float4 v3 = x4[myRow * 4 + 3];
        xv[0]=v0.x;  xv[1]=v0.y;  xv[2]=v0.z;  xv[3]=v0.w;
        xv[4]=v1.x;  xv[5]=v1.y;  xv[6]=v1.z;  xv[7]=v1.w;
        xv[8]=v2.x;  xv[9]=v2.y;  xv[10]=v2.z; xv[11]=v2.w;
        xv[12]=v3.x; xv[13]=v3.y; xv[14]=v3.z; xv[15]=v3.w;
    }

    // Compute phase: lane = row; each warp owns a column range.
    // STS bank check: word start = (700*row + 4*v4) mod 32 = 28*row + 4*v4;
    // rows within an 8-lane phase hit 8 disjoint 4-word slots -> conflict-free.
    float4* __restrict__ shrow = sh + lane * SH_STRIDE;
    if      (warp == 0) compute_cols<0,   44>(xv, shrow);
    else if (warp == 1) compute_cols<44,  88>(xv, shrow);
    else if (warp == 2) compute_cols<88, 132>(xv, shrow);
    else                compute_cols<132,174>(xv, shrow);

    __syncthreads();

    // Copy-out: tile is contiguous in global (32 rows * 2784B = 89,088B,
    // 512B-aligned per block). Flat index g -> smem index g + g/174.
    float4* __restrict__ oflat = out4 + (long long)blockIdx.x * TILE_V4;

#pragma unroll 4
    for (int i = 0; i < TILE_V4 / BLOCK_T; ++i) {     // 43 full iterations
        const int g   = i * BLOCK_T + tid;
        const int row = g / OUT_V4;
        oflat[g] = sh[g + row];
    }
    {                                                  // tail: 64 float4
        const int g = (TILE_V4 / BLOCK_T) * BLOCK_T + tid;
        if (g < TILE_V4) {
            const int row = g / OUT_V4;
            oflat[g] = sh[g + row];
        }
    }
}

extern "C" void kernel_launch(void* const* d_in, const int* in_sizes, int n_in,
                              void* d_out, int out_size)
{
    const float4* x4 = (const float4*)d_in[0];
    float4* out4 = (float4*)d_out;
    (void)in_sizes; (void)n_in; (void)out_size;

    cudaFuncSetAttribute(luk_kernel,
                         cudaFuncAttributeMaxDynamicSharedMemorySize,
                         SMEM_BYTES);

    const int grid = N_ROWS / ROWS_PB;   // 4096 blocks
    luk_kernel<<<grid, BLOCK_T, SMEM_BYTES>>>(x4, out4);
}